// round 16
// baseline (speedup 1.0000x reference)
#include <cuda_runtime.h>
#include <cuda_fp16.h>
#include <cstdint>

// ---------------------------------------------------------------------------
// GCN via mma.sync fp16 GEMMs (fp32 accumulate). TWO launches total.
//   GEMM1 (fully fused): H^T = W^T @ X^T. Reads w fp32 (transpose-convert in
//     smem) and X fp32 (convert in smem). 64 rider blocks convert adj->fp16.
//   GEMM2: Out[b] = adj @ H_b (R8/R14 kernel, measured optimum).
// ---------------------------------------------------------------------------

#define N_NODES 512
#define N_BATCH 64
#define D_IN    256
#define D_OUT   256
#define M_ALL   (N_NODES * N_BATCH)   // 32768

// ---- GEMM2 config (R8) ----
#define BM 128
#define BN 128
#define BKB 64
#define NTHREADS 256
#define S_STAGES 3
#define PITCHB 144
#define TILEB (128 * PITCHB)
#define STAGEB (2 * TILEB)
#define SMEM_TOTAL (S_STAGES * STAGEB) // 110592
#define OFF_A 0
#define OFF_B TILEB

// ---- GEMM1 fully-fused config (BK=32 fp16, 2-stage rings) ----
#define F_A32_PITCH 528                    // 128 fp32 + 16B pad
#define F_A32_STAGE (32 * F_A32_PITCH)     // 16896
#define F_A16_PITCH 80
#define F_A16_STAGE (128 * F_A16_PITCH)    // 10240
#define F_B32_PITCH 144
#define F_B32_STAGE (128 * F_B32_PITCH)    // 18432
#define F_OFF_A32 0
#define F_OFF_A16 (2 * F_A32_STAGE)                  // 33792
#define F_OFF_B32 (F_OFF_A16 + 2 * F_A16_STAGE)      // 54272
#define F_OFF_B16 (F_OFF_B32 + 2 * F_B32_STAGE)      // 91136
#define F_SMEM    (F_OFF_B16 + 2 * F_A16_STAGE)      // 111616

// device scratch
__device__ __half g_adjh[N_NODES * N_NODES];
__device__ __half g_h[(size_t)D_OUT * M_ALL];

// ---------------- helpers ----------------
__device__ __forceinline__ uint32_t smem_u32(const void* p) {
    uint32_t a;
    asm("{ .reg .u64 t; cvta.to.shared.u64 t, %1; cvt.u32.u64 %0, t; }" : "=r"(a) : "l"(p));
    return a;
}
__device__ __forceinline__ void cp16(uint32_t dst, const void* src) {
    asm volatile("cp.async.cg.shared.global [%0], [%1], 16;" :: "r"(dst), "l"(src) : "memory");
}
__device__ __forceinline__ void cp_commit() {
    asm volatile("cp.async.commit_group;" ::: "memory");
}
template <int N>
__device__ __forceinline__ void cp_wait() {
    asm volatile("cp.async.wait_group %0;" :: "n"(N) : "memory");
}
__device__ __forceinline__ void ldsm_x4(uint32_t* r, uint32_t addr) {
    asm volatile("ldmatrix.sync.aligned.m8n8.x4.shared.b16 {%0,%1,%2,%3}, [%4];"
                 : "=r"(r[0]), "=r"(r[1]), "=r"(r[2]), "=r"(r[3]) : "r"(addr));
}
__device__ __forceinline__ void mma_f16(float* c, const uint32_t* a, const uint32_t* b) {
    asm volatile(
        "mma.sync.aligned.m16n8k16.row.col.f32.f16.f16.f32 "
        "{%0,%1,%2,%3}, {%4,%5,%6,%7}, {%8,%9}, {%0,%1,%2,%3};"
        : "+f"(c[0]), "+f"(c[1]), "+f"(c[2]), "+f"(c[3])
        : "r"(a[0]), "r"(a[1]), "r"(a[2]), "r"(a[3]), "r"(b[0]), "r"(b[1]));
}
__device__ __forceinline__ uint2 cvt_f4(float4 a) {
    __half2 h0 = __float22half2_rn(make_float2(a.x, a.y));
    __half2 h1 = __float22half2_rn(make_float2(a.z, a.w));
    return make_uint2(*(uint32_t*)&h0, *(uint32_t*)&h1);
}

// ---------------- GEMM1 fully fused ----------------
// Blocks x<256: GEMM tile. Blocks x>=256: adj fp32->fp16 rider (64 slices).
__global__ __launch_bounds__(NTHREADS, 2)
void gemm1_fused(const float* __restrict__ w,     // [din=256][dout=256] fp32
                 const float* __restrict__ X,     // [32768][256] fp32
                 const float* __restrict__ adj,   // [512][512] fp32
                 __half* __restrict__ Ch,         // H^T [256][32768] fp16
                 __half* __restrict__ adjh) {
    const int tid = threadIdx.x;

    if (blockIdx.x >= 256) {
        // adj convert rider: slice 0..63
        const int slice = (blockIdx.x - 256) * 2 + blockIdx.y;
        const size_t t = (size_t)slice * 256 + tid;
        const float4* src = (const float4*)adj + t * 4;
        float4 v0 = src[0], v1 = src[1], v2 = src[2], v3 = src[3];
        uint2 a0 = cvt_f4(v0), a1 = cvt_f4(v1), a2 = cvt_f4(v2), a3 = cvt_f4(v3);
        uint4* dst = (uint4*)adjh + t * 2;
        dst[0] = make_uint4(a0.x, a0.y, a1.x, a1.y);
        dst[1] = make_uint4(a2.x, a2.y, a3.x, a3.y);
        return;
    }

    extern __shared__ char smem[];
    const uint32_t sb = smem_u32(smem);
    const int lane = tid & 31;
    const int wid = tid >> 5;
    const int wm = (wid & 3) * 32;
    const int wn = (wid >> 2) * 64;

    const int m0 = blockIdx.y * BM;   // dout tile (0,128)
    const int n0 = blockIdx.x * BN;   // node tile

    // load maps (both matrices: row = tid>>3, chunk = tid&7)
    const int lrow = tid >> 3;        // 0..31
    const int lcol = tid & 7;         // chunk16B

    // A convert map: kk = din row 0..31, mm0 = dout segment base
    const int kk = tid >> 3;
    const int mm0 = (tid & 7) * 16;
    // B convert map (as R14)
    const int vrow = tid >> 1;
    const int vcol = (tid & 1) * 2;

    // ldmatrix addresses (pitch 80)
    const uint32_t aOff = (uint32_t)((wm + (lane & 15)) * F_A16_PITCH + ((lane >> 4) << 4));
    const uint32_t bOff = (uint32_t)((wn + ((lane >> 4) << 3) + (lane & 7)) * F_A16_PITCH +
                                     (((lane >> 3) & 1) << 4));

    float acc[2][8][4];
#pragma unroll
    for (int mt = 0; mt < 2; mt++)
#pragma unroll
        for (int nt = 0; nt < 8; nt++)
#pragma unroll
            for (int q = 0; q < 4; q++) acc[mt][nt][q] = 0.0f;

    const int NT = D_IN / 32;   // 8 stages

    auto load_stage = [&](int s) {
        const uint32_t stA = sb + F_OFF_A32 + (uint32_t)((s & 1) * F_A32_STAGE);
        const uint32_t stB = sb + F_OFF_B32 + (uint32_t)((s & 1) * F_B32_STAGE);
        const int k16 = s * 32;
        // A32: w rows [k16, k16+32) x dout cols [m0, m0+128): 4 chunks/thread
#pragma unroll
        for (int j = 0; j < 4; j++) {
            cp16(stA + (uint32_t)(lrow * F_A32_PITCH + (lcol + 8 * j) * 16),
                 w + (size_t)(k16 + lrow) * D_OUT + m0 + (lcol + 8 * j) * 4);
        }
        // B32: X rows [n0, n0+128) x din cols [k16, k16+32): 4 chunks/thread
#pragma unroll
        for (int j = 0; j < 4; j++) {
            int r = lrow + j * 32;
            cp16(stB + (uint32_t)(r * F_B32_PITCH + lcol * 16),
                 X + (size_t)(n0 + r) * D_IN + k16 + lcol * 4);
        }
        cp_commit();
    };

    load_stage(0);
    load_stage(1);

    for (int t = 0; t < NT; t++) {
        cp_wait<1>();
        __syncthreads();

        const int slot = t & 1;
        const uint32_t srcA = (uint32_t)(F_OFF_A32 + slot * F_A32_STAGE);
        const uint32_t dstA = (uint32_t)(F_OFF_A16 + slot * F_A16_STAGE);
        const uint32_t srcB = (uint32_t)(F_OFF_B32 + slot * F_B32_STAGE);
        const uint32_t dstB = (uint32_t)(F_OFF_B16 + slot * F_A16_STAGE);

        // convert A: transpose w[kk][mm] -> A16[mm][kk]
        {
            float f[16];
#pragma unroll
            for (int j = 0; j < 4; j++) {
                float4 v = *(const float4*)(smem + srcA + kk * F_A32_PITCH + mm0 * 4 + j * 16);
                f[4 * j + 0] = v.x; f[4 * j + 1] = v.y; f[4 * j + 2] = v.z; f[4 * j + 3] = v.w;
            }
#pragma unroll
            for (int i = 0; i < 16; i++)
                *(__half*)(smem + dstA + (mm0 + i) * F_A16_PITCH + kk * 2) = __float2half_rn(f[i]);
        }
        // convert B (as R14)
#pragma unroll
        for (int j = 0; j < 2; j++) {
            int oc = vcol + j;
            float4 f0 = *(const float4*)(smem + srcB + vrow * F_B32_PITCH + oc * 32);
            float4 f1 = *(const float4*)(smem + srcB + vrow * F_B32_PITCH + oc * 32 + 16);
            uint2 p0 = cvt_f4(f0);
            uint2 p1 = cvt_f4(f1);
            *(uint4*)(smem + dstB + vrow * F_A16_PITCH + oc * 16) =
                make_uint4(p0.x, p0.y, p1.x, p1.y);
        }
        __syncthreads();

        // prefetch t+2 into slot (t&1) of the fp32 rings (just fully read)
        if (t + 2 < NT) {
            load_stage(t + 2);
        } else {
            cp_commit();
        }

        // compute stage t from fp16 regions
        const uint32_t A16 = sb + dstA;
        const uint32_t B16 = sb + dstB;
#pragma unroll
        for (int ko = 0; ko < 2; ko++) {
            uint32_t ah[2][4];
#pragma unroll
            for (int mt = 0; mt < 2; mt++)
                ldsm_x4(ah[mt], A16 + aOff + mt * 16 * F_A16_PITCH + ko * 32);
#pragma unroll
            for (int np = 0; np < 4; np++) {
                uint32_t bh[4];
                ldsm_x4(bh, B16 + bOff + np * 16 * F_A16_PITCH + ko * 32);
#pragma unroll
                for (int sub = 0; sub < 2; sub++)
#pragma unroll
                    for (int mt = 0; mt < 2; mt++)
                        mma_f16(acc[mt][np * 2 + sub], ah[mt], bh + sub * 2);
            }
        }
        __syncthreads();
    }

    // epilogue -> H^T fp16, ldc = M_ALL
    const int l4 = lane >> 2;
    const int lp = lane & 3;
#pragma unroll
    for (int mt = 0; mt < 2; mt++) {
#pragma unroll
        for (int nt = 0; nt < 8; nt++) {
            const float* c = acc[mt][nt];
            long m = m0 + wm + mt * 16 + l4;
            long n = n0 + wn + nt * 8 + lp * 2;
            __half2 p0 = __float22half2_rn(make_float2(c[0], c[1]));
            __half2 p1 = __float22half2_rn(make_float2(c[2], c[3]));
            *(uint32_t*)(Ch + m * M_ALL + n) = *(uint32_t*)&p0;
            *(uint32_t*)(Ch + (m + 8) * M_ALL + n) = *(uint32_t*)&p1;
        }
    }
}

// ---------------- GEMM2 (R8/R14 kernel, fp32 out) ----------------
__global__ __launch_bounds__(NTHREADS, 2)
void hgemm_f16(const __half* __restrict__ A, int lda,
               const __half* __restrict__ B, int ldb, long bStride,
               float* __restrict__ Cf, int ldc, long cStride, int K) {
    extern __shared__ char smem[];
    const uint32_t sb = smem_u32(smem);
    const int tid = threadIdx.x;
    const int lane = tid & 31;
    const int wid = tid >> 5;
    const int wm = (wid & 3) * 32;
    const int wn = (wid >> 2) * 64;

    const int m0 = blockIdx.y * BM;
    const int n0 = blockIdx.x * BN;
    const long bz = blockIdx.z;
    B += bz * bStride;

    const int cr = tid >> 3;
    const int cc = tid & 7;
    const uint32_t soBase = (uint32_t)(cc * 16);
    const int gcol = cc * 8;

    const uint32_t aOff = (uint32_t)((wm + (lane & 15)) * PITCHB + ((lane >> 4) << 4));
    const uint32_t bOff = (uint32_t)((wn + ((lane >> 4) << 3) + (lane & 7)) * PITCHB +
                                     (((lane >> 3) & 1) << 4));

    float acc[2][8][4];
#pragma unroll
    for (int mt = 0; mt < 2; mt++)
#pragma unroll
        for (int nt = 0; nt < 8; nt++)
#pragma unroll
            for (int q = 0; q < 4; q++) acc[mt][nt][q] = 0.0f;

    const int NT = K / BKB;

    auto load_stage = [&](int t) {
        const uint32_t st = sb + (uint32_t)((t % S_STAGES) * STAGEB);
        const int k0 = t * BKB + gcol;
#pragma unroll
        for (int j = 0; j < 4; j++) {
            int r = cr + j * 32;
            uint32_t so = (uint32_t)(r * PITCHB) + soBase;
            cp16(st + OFF_A + so, A + (size_t)(m0 + r) * lda + k0);
            cp16(st + OFF_B + so, B + (size_t)(n0 + r) * ldb + k0);
        }
        cp_commit();
    };

    load_stage(0);
    if (NT > 1) load_stage(1);

    for (int t = 0; t < NT; t++) {
        cp_wait<1>();
        __syncthreads();

        const uint32_t st = sb + (uint32_t)((t % S_STAGES) * STAGEB);

        uint32_t ah[2][2][4];
#pragma unroll
        for (int mt = 0; mt < 2; mt++)
            ldsm_x4(ah[0][mt], st + OFF_A + aOff + mt * 16 * PITCHB);

#pragma unroll
        for (int ko = 0; ko < 4; ko++) {
            const int cur = ko & 1, nxt = cur ^ 1;
            if (ko < 3) {
#pragma unroll
                for (int mt = 0; mt < 2; mt++)
                    ldsm_x4(ah[nxt][mt], st + OFF_A + aOff + mt * 16 * PITCHB + (ko + 1) * 32);
            }
#pragma unroll
            for (int np = 0; np < 4; np++) {
                uint32_t bh[4];
                ldsm_x4(bh, st + OFF_B + bOff + np * 16 * PITCHB + ko * 32);
#pragma unroll
                for (int sub = 0; sub < 2; sub++)
#pragma unroll
                    for (int mt = 0; mt < 2; mt++)
                        mma_f16(acc[mt][np * 2 + sub], ah[cur][mt], bh + sub * 2);
            }
        }

        __syncthreads();
        if (t + 2 < NT) {
            load_stage(t + 2);
        } else {
            cp_commit();
        }
    }

    const int l4 = lane >> 2;
    const int lp = lane & 3;
#pragma unroll
    for (int mt = 0; mt < 2; mt++) {
#pragma unroll
        for (int nt = 0; nt < 8; nt++) {
            const float* c = acc[mt][nt];
            long m = m0 + wm + mt * 16 + l4;
            long n = n0 + wn + nt * 8 + lp * 2;
            float* base = Cf + bz * cStride;
            *(float2*)(base + m * ldc + n) = make_float2(c[0], c[1]);
            *(float2*)(base + (m + 8) * ldc + n) = make_float2(c[2], c[3]);
        }
    }
}

// ---------------- launch ----------------
extern "C" void kernel_launch(void* const* d_in, const int* in_sizes, int n_in,
                              void* d_out, int out_size) {
    const float* x      = (const float*)d_in[0];
    const float* weight = (const float*)d_in[2];
    const float* adj    = (const float*)d_in[3];
    float* out          = (float*)d_out;

    __half *adjh, *h;
    cudaGetSymbolAddress((void**)&adjh, g_adjh);
    cudaGetSymbolAddress((void**)&h, g_h);

    cudaFuncSetAttribute(gemm1_fused, cudaFuncAttributeMaxDynamicSharedMemorySize, F_SMEM);
    cudaFuncSetAttribute(hgemm_f16, cudaFuncAttributeMaxDynamicSharedMemorySize, SMEM_TOTAL);

    // GEMM1 fused (+ adj convert riders): grid x = 256 GEMM tiles + 32 riders
    {
        dim3 grid(256 + 32, D_OUT / BM, 1);   // (288, 2)
        gemm1_fused<<<grid, NTHREADS, F_SMEM>>>(weight, x, adj, h, adjh);
    }
    // GEMM2: Out[b] = adj @ H_b
    {
        dim3 grid(D_OUT / BN, N_NODES / BM, N_BATCH);
        hgemm_f16<<<grid, NTHREADS, SMEM_TOTAL>>>(
            adjh, N_NODES,
            h, M_ALL, (long)N_NODES,
            out, D_OUT, (long)(N_NODES * D_OUT),
            N_NODES);
    }
}

// round 17
// speedup vs baseline: 1.3732x; 1.3732x over previous
#include <cuda_runtime.h>
#include <cuda_fp16.h>
#include <cstdint>

// ---------------------------------------------------------------------------
// GCN via mma.sync fp16 GEMMs (fp32 accumulate). Three launches:
//   1) cvt_w: w fp32 -> w^T fp16 (tiled transpose; needed by GEMM1)
//   2) GEMM1 (fused x-cvt) + adj-convert rider blocks
//   3) GEMM2: Out[b] = adj @ H_b  (R8/R14 kernel)
// R17 = R14 with cvt_small split by dependency: adj convert rides GEMM1.
// ---------------------------------------------------------------------------

#define N_NODES 512
#define N_BATCH 64
#define D_IN    256
#define D_OUT   256
#define M_ALL   (N_NODES * N_BATCH)   // 32768

// ---- GEMM2 (R8) config ----
#define BM 128
#define BN 128
#define BKB 64
#define NTHREADS 256
#define S_STAGES 3
#define PITCHB 144
#define TILEB (128 * PITCHB)
#define STAGEB (2 * TILEB)
#define SMEM_TOTAL (S_STAGES * STAGEB) // 110592
#define OFF_A 0
#define OFF_B TILEB

// ---- GEMM1 fused config (R14: BK=32 fp16, 3-stage B32 ring) ----
#define G1_PITCH_A   80
#define G1_PITCH_B32 144
#define G1_A_STAGE   (128 * G1_PITCH_A)   // 10240
#define G1_B32_STAGE (128 * G1_PITCH_B32) // 18432
#define G1_OFF_A     0
#define G1_OFF_B32   (3 * G1_A_STAGE)
#define G1_OFF_B16   (G1_OFF_B32 + 3 * G1_B32_STAGE)
#define G1_SMEM      (G1_OFF_B16 + 2 * G1_A_STAGE)       // 106496

// device scratch
__device__ __half g_wth[D_OUT * D_IN];
__device__ __half g_adjh[N_NODES * N_NODES];
__device__ __half g_h[(size_t)D_OUT * M_ALL];

// ---------------- helpers ----------------
__device__ __forceinline__ uint32_t smem_u32(const void* p) {
    uint32_t a;
    asm("{ .reg .u64 t; cvta.to.shared.u64 t, %1; cvt.u32.u64 %0, t; }" : "=r"(a) : "l"(p));
    return a;
}
__device__ __forceinline__ void cp16(uint32_t dst, const void* src) {
    asm volatile("cp.async.cg.shared.global [%0], [%1], 16;" :: "r"(dst), "l"(src) : "memory");
}
__device__ __forceinline__ void cp_commit() {
    asm volatile("cp.async.commit_group;" ::: "memory");
}
template <int N>
__device__ __forceinline__ void cp_wait() {
    asm volatile("cp.async.wait_group %0;" :: "n"(N) : "memory");
}
__device__ __forceinline__ void ldsm_x4(uint32_t* r, uint32_t addr) {
    asm volatile("ldmatrix.sync.aligned.m8n8.x4.shared.b16 {%0,%1,%2,%3}, [%4];"
                 : "=r"(r[0]), "=r"(r[1]), "=r"(r[2]), "=r"(r[3]) : "r"(addr));
}
__device__ __forceinline__ void mma_f16(float* c, const uint32_t* a, const uint32_t* b) {
    asm volatile(
        "mma.sync.aligned.m16n8k16.row.col.f32.f16.f16.f32 "
        "{%0,%1,%2,%3}, {%4,%5,%6,%7}, {%8,%9}, {%0,%1,%2,%3};"
        : "+f"(c[0]), "+f"(c[1]), "+f"(c[2]), "+f"(c[3])
        : "r"(a[0]), "r"(a[1]), "r"(a[2]), "r"(a[3]), "r"(b[0]), "r"(b[1]));
}
__device__ __forceinline__ uint2 cvt_f4(float4 a) {
    __half2 h0 = __float22half2_rn(make_float2(a.x, a.y));
    __half2 h1 = __float22half2_rn(make_float2(a.z, a.w));
    return make_uint2(*(uint32_t*)&h0, *(uint32_t*)&h1);
}

// ---------------- cvt_w: tiled w transpose (64 blocks) ----------------
__global__ __launch_bounds__(256) void cvt_w(const float* __restrict__ w,
                                             __half* __restrict__ wth) {
    __shared__ __half sm[32][33];
    const int bx = blockIdx.x & 7;          // col tile of w
    const int by = blockIdx.x >> 3;         // row tile of w
    const int tx = threadIdx.x & 31;
    const int ty = threadIdx.x >> 5;        // 0..7
#pragma unroll
    for (int j = 0; j < 4; j++) {
        int r = ty + j * 8;
        sm[r][tx] = __float2half_rn(w[(size_t)(by * 32 + r) * D_OUT + bx * 32 + tx]);
    }
    __syncthreads();
#pragma unroll
    for (int j = 0; j < 4; j++) {
        int r = ty + j * 8;
        wth[(size_t)(bx * 32 + r) * D_IN + by * 32 + tx] = sm[tx][r];
    }
}

// ---------------- GEMM1 fused (R14) + adj riders ----------------
// Blocks x<256: GEMM tile. Blocks x>=256: adj fp32->fp16 rider.
__global__ __launch_bounds__(NTHREADS, 2)
void gemm1_fused(const __half* __restrict__ A,    // wth fp16 [256][256]
                 const float* __restrict__ X,     // [32768][256] fp32
                 const float* __restrict__ adj,   // [512][512] fp32
                 __half* __restrict__ Ch,         // H^T [256][32768]
                 __half* __restrict__ adjh) {
    const int tid = threadIdx.x;

    if (blockIdx.x >= 256) {
        // adj convert rider: 64 slices (32 x-blocks * 2 y)
        const int slice = (blockIdx.x - 256) * 2 + blockIdx.y;
        const size_t t = (size_t)slice * 256 + tid;
        const float4* src = (const float4*)adj + t * 4;
        float4 v0 = src[0], v1 = src[1], v2 = src[2], v3 = src[3];
        uint2 a0 = cvt_f4(v0), a1 = cvt_f4(v1), a2 = cvt_f4(v2), a3 = cvt_f4(v3);
        uint4* dst = (uint4*)adjh + t * 2;
        dst[0] = make_uint4(a0.x, a0.y, a1.x, a1.y);
        dst[1] = make_uint4(a2.x, a2.y, a3.x, a3.y);
        return;
    }

    extern __shared__ char smem[];
    const uint32_t sb = smem_u32(smem);
    const int lane = tid & 31;
    const int wid = tid >> 5;
    const int wm = (wid & 3) * 32;
    const int wn = (wid >> 2) * 64;

    const int m0 = blockIdx.y * BM;
    const int n0 = blockIdx.x * BN;

    const int arow = tid >> 2;
    const int acol = tid & 3;
    const int brow = tid >> 3;
    const int bcol = tid & 7;
    const int vrow = tid >> 1;
    const int vcol = (tid & 1) * 2;

    const uint32_t aOff = (uint32_t)((wm + (lane & 15)) * G1_PITCH_A + ((lane >> 4) << 4));
    const uint32_t bOff = (uint32_t)((wn + ((lane >> 4) << 3) + (lane & 7)) * G1_PITCH_A +
                                     (((lane >> 3) & 1) << 4));

    float acc[2][8][4];
#pragma unroll
    for (int mt = 0; mt < 2; mt++)
#pragma unroll
        for (int nt = 0; nt < 8; nt++)
#pragma unroll
            for (int q = 0; q < 4; q++) acc[mt][nt][q] = 0.0f;

    const int NT = D_IN / 32;   // 8 stages

    auto load_stage = [&](int s) {
        const uint32_t stA = sb + G1_OFF_A + (uint32_t)((s % 3) * G1_A_STAGE);
        const uint32_t stB = sb + G1_OFF_B32 + (uint32_t)((s % 3) * G1_B32_STAGE);
        const int k16 = s * 32;
#pragma unroll
        for (int j = 0; j < 2; j++) {
            int r = arow + j * 64;
            cp16(stA + (uint32_t)(r * G1_PITCH_A + acol * 16),
                 A + (size_t)(m0 + r) * D_IN + k16 + acol * 8);
        }
#pragma unroll
        for (int j = 0; j < 4; j++) {
            int r = brow + j * 32;
            cp16(stB + (uint32_t)(r * G1_PITCH_B32 + bcol * 16),
                 X + (size_t)(n0 + r) * D_IN + k16 + bcol * 4);
        }
        cp_commit();
    };

    load_stage(0);
    load_stage(1);

    for (int t = 0; t < NT; t++) {
        cp_wait<1>();
        __syncthreads();

        const uint32_t srcB = sb + G1_OFF_B32 + (uint32_t)((t % 3) * G1_B32_STAGE);
        const uint32_t dstB = sb + G1_OFF_B16 + (uint32_t)((t & 1) * G1_A_STAGE);
#pragma unroll
        for (int j = 0; j < 2; j++) {
            int oc = vcol + j;
            float4 f0 = *(const float4*)(smem + (srcB - sb) + vrow * G1_PITCH_B32 + oc * 32);
            float4 f1 = *(const float4*)(smem + (srcB - sb) + vrow * G1_PITCH_B32 + oc * 32 + 16);
            uint2 p0 = cvt_f4(f0);
            uint2 p1 = cvt_f4(f1);
            *(uint4*)(smem + (dstB - sb) + vrow * G1_PITCH_A + oc * 16) =
                make_uint4(p0.x, p0.y, p1.x, p1.y);
        }
        __syncthreads();

        const uint32_t stA = sb + G1_OFF_A + (uint32_t)((t % 3) * G1_A_STAGE);
#pragma unroll
        for (int ko = 0; ko < 2; ko++) {
            uint32_t ah[2][4];
#pragma unroll
            for (int mt = 0; mt < 2; mt++)
                ldsm_x4(ah[mt], stA + aOff + mt * 16 * G1_PITCH_A + ko * 32);
#pragma unroll
            for (int np = 0; np < 4; np++) {
                uint32_t bh[4];
                ldsm_x4(bh, dstB + bOff + np * 16 * G1_PITCH_A + ko * 32);
#pragma unroll
                for (int sub = 0; sub < 2; sub++)
#pragma unroll
                    for (int mt = 0; mt < 2; mt++)
                        mma_f16(acc[mt][np * 2 + sub], ah[mt], bh + sub * 2);
            }
        }

        if (t + 2 < NT) {
            load_stage(t + 2);
        } else {
            cp_commit();
        }
    }

    const int l4 = lane >> 2;
    const int lp = lane & 3;
#pragma unroll
    for (int mt = 0; mt < 2; mt++) {
#pragma unroll
        for (int nt = 0; nt < 8; nt++) {
            const float* c = acc[mt][nt];
            long m = m0 + wm + mt * 16 + l4;
            long n = n0 + wn + nt * 8 + lp * 2;
            __half2 p0 = __float22half2_rn(make_float2(c[0], c[1]));
            __half2 p1 = __float22half2_rn(make_float2(c[2], c[3]));
            *(uint32_t*)(Ch + m * M_ALL + n) = *(uint32_t*)&p0;
            *(uint32_t*)(Ch + (m + 8) * M_ALL + n) = *(uint32_t*)&p1;
        }
    }
}

// ---------------- GEMM2 (R8/R14 kernel, fp32 out) ----------------
__global__ __launch_bounds__(NTHREADS, 2)
void hgemm_f16(const __half* __restrict__ A, int lda,
               const __half* __restrict__ B, int ldb, long bStride,
               float* __restrict__ Cf, int ldc, long cStride, int K) {
    extern __shared__ char smem[];
    const uint32_t sb = smem_u32(smem);
    const int tid = threadIdx.x;
    const int lane = tid & 31;
    const int wid = tid >> 5;
    const int wm = (wid & 3) * 32;
    const int wn = (wid >> 2) * 64;

    const int m0 = blockIdx.y * BM;
    const int n0 = blockIdx.x * BN;
    const long bz = blockIdx.z;
    B += bz * bStride;

    const int cr = tid >> 3;
    const int cc = tid & 7;
    const uint32_t soBase = (uint32_t)(cc * 16);
    const int gcol = cc * 8;

    const uint32_t aOff = (uint32_t)((wm + (lane & 15)) * PITCHB + ((lane >> 4) << 4));
    const uint32_t bOff = (uint32_t)((wn + ((lane >> 4) << 3) + (lane & 7)) * PITCHB +
                                     (((lane >> 3) & 1) << 4));

    float acc[2][8][4];
#pragma unroll
    for (int mt = 0; mt < 2; mt++)
#pragma unroll
        for (int nt = 0; nt < 8; nt++)
#pragma unroll
            for (int q = 0; q < 4; q++) acc[mt][nt][q] = 0.0f;

    const int NT = K / BKB;

    auto load_stage = [&](int t) {
        const uint32_t st = sb + (uint32_t)((t % S_STAGES) * STAGEB);
        const int k0 = t * BKB + gcol;
#pragma unroll
        for (int j = 0; j < 4; j++) {
            int r = cr + j * 32;
            uint32_t so = (uint32_t)(r * PITCHB) + soBase;
            cp16(st + OFF_A + so, A + (size_t)(m0 + r) * lda + k0);
            cp16(st + OFF_B + so, B + (size_t)(n0 + r) * ldb + k0);
        }
        cp_commit();
    };

    load_stage(0);
    if (NT > 1) load_stage(1);

    for (int t = 0; t < NT; t++) {
        cp_wait<1>();
        __syncthreads();

        const uint32_t st = sb + (uint32_t)((t % S_STAGES) * STAGEB);

        uint32_t ah[2][2][4];
#pragma unroll
        for (int mt = 0; mt < 2; mt++)
            ldsm_x4(ah[0][mt], st + OFF_A + aOff + mt * 16 * PITCHB);

#pragma unroll
        for (int ko = 0; ko < 4; ko++) {
            const int cur = ko & 1, nxt = cur ^ 1;
            if (ko < 3) {
#pragma unroll
                for (int mt = 0; mt < 2; mt++)
                    ldsm_x4(ah[nxt][mt], st + OFF_A + aOff + mt * 16 * PITCHB + (ko + 1) * 32);
            }
#pragma unroll
            for (int np = 0; np < 4; np++) {
                uint32_t bh[4];
                ldsm_x4(bh, st + OFF_B + bOff + np * 16 * PITCHB + ko * 32);
#pragma unroll
                for (int sub = 0; sub < 2; sub++)
#pragma unroll
                    for (int mt = 0; mt < 2; mt++)
                        mma_f16(acc[mt][np * 2 + sub], ah[cur][mt], bh + sub * 2);
            }
        }

        __syncthreads();
        if (t + 2 < NT) {
            load_stage(t + 2);
        } else {
            cp_commit();
        }
    }

    const int l4 = lane >> 2;
    const int lp = lane & 3;
#pragma unroll
    for (int mt = 0; mt < 2; mt++) {
#pragma unroll
        for (int nt = 0; nt < 8; nt++) {
            const float* c = acc[mt][nt];
            long m = m0 + wm + mt * 16 + l4;
            long n = n0 + wn + nt * 8 + lp * 2;
            float* base = Cf + bz * cStride;
            *(float2*)(base + m * ldc + n) = make_float2(c[0], c[1]);
            *(float2*)(base + (m + 8) * ldc + n) = make_float2(c[2], c[3]);
        }
    }
}

// ---------------- launch ----------------
extern "C" void kernel_launch(void* const* d_in, const int* in_sizes, int n_in,
                              void* d_out, int out_size) {
    const float* x      = (const float*)d_in[0];
    const float* weight = (const float*)d_in[2];
    const float* adj    = (const float*)d_in[3];
    float* out          = (float*)d_out;

    __half *wth, *adjh, *h;
    cudaGetSymbolAddress((void**)&wth, g_wth);
    cudaGetSymbolAddress((void**)&adjh, g_adjh);
    cudaGetSymbolAddress((void**)&h, g_h);

    cudaFuncSetAttribute(gemm1_fused, cudaFuncAttributeMaxDynamicSharedMemorySize, G1_SMEM);
    cudaFuncSetAttribute(hgemm_f16, cudaFuncAttributeMaxDynamicSharedMemorySize, SMEM_TOTAL);

    // 1) w transpose (needed by GEMM1)
    cvt_w<<<64, 256>>>(weight, wth);

    // 2) GEMM1 fused (+ adj riders)
    {
        dim3 grid(256 + 32, D_OUT / BM, 1);   // (288, 2)
        gemm1_fused<<<grid, NTHREADS, G1_SMEM>>>(wth, x, adj, h, adjh);
    }
    // 3) GEMM2: Out[b] = adj @ H_b
    {
        dim3 grid(D_OUT / BN, N_NODES / BM, N_BATCH);
        hgemm_f16<<<grid, NTHREADS, SMEM_TOTAL>>>(
            adjh, N_NODES,
            h, M_ALL, (long)N_NODES,
            out, D_OUT, (long)(N_NODES * D_OUT),
            N_NODES);
    }
}